// round 7
// baseline (speedup 1.0000x reference)
#include <cuda_runtime.h>

// LSTM1: B=4096, T=2048, I=6, H=2.
// 2 threads per sequence-lane split (parity p owns hidden lane p) AND
// 2 independent sequences per thread (A, B), explicitly interleaved each
// step. With only 1 warp/SMSP the recurrence chain's stall cycles were
// exposed (~44% idle issue slots); sequence B's chain fills sequence A's
// stalls and vice versa. Sigmoid 0.5 pre-folded into i/f/o weights+biases.
// 4096 threads = 128 warps, one per SM.

#define B_DIM 4096
#define T_DIM 2048
#define I_DIM 6

__device__ __forceinline__ float tanh_ap(float x) {
    float y; asm("tanh.approx.f32 %0, %1;" : "=f"(y) : "f"(x)); return y;
}

// One recurrence step for one lane of one sequence.
// gates = (bias + W_x*x) [6 FMAs, off-chain] + h_own*whO + h_peer*whP.
__device__ __forceinline__ void lstm_step(
    float x0, float x1, float x2, float x3, float x4, float x5,
    const float (&w)[4][6], const float (&whO)[4], const float (&whP)[4],
    const float (&bs)[4],
    float& c, float& h_own, float& h_peer)
{
    float g[4];
#pragma unroll
    for (int r = 0; r < 4; r++) {
        float a = fmaf(x0, w[r][0], bs[r]);
        a = fmaf(x1, w[r][1], a);
        a = fmaf(x2, w[r][2], a);
        float b2 = x3 * w[r][3];
        b2 = fmaf(x4, w[r][4], b2);
        b2 = fmaf(x5, w[r][5], b2);
        a = a + b2;
        // h terms LAST: shortest dependency path from previous step's h.
        a = fmaf(h_own, whO[r], a);
        a = fmaf(h_peer, whP[r], a);
        g[r] = a;
    }
    const float ig = fmaf(tanh_ap(g[0]), 0.5f, 0.5f);
    const float fg = fmaf(tanh_ap(g[1]), 0.5f, 0.5f);
    const float gg = tanh_ap(g[2]);
    const float og = fmaf(tanh_ap(g[3]), 0.5f, 0.5f);

    c = fmaf(fg, c, ig * gg);
    h_own = og * tanh_ap(c);
    h_peer = __shfl_xor_sync(0xFFFFFFFFu, h_own, 1);
}

__global__ void __launch_bounds__(32, 1) lstm_fused_kernel(
    const float* __restrict__ x,
    const float* __restrict__ w_ih, const float* __restrict__ w_hh,
    const float* __restrict__ b_ih, const float* __restrict__ b_hh,
    const float* __restrict__ fc1_w, const float* __restrict__ fc1_b,
    const float* __restrict__ fc_w, const float* __restrict__ fc_b,
    float* __restrict__ out)
{
    // 4096 threads; lane pair (2j, 2j+1) = lanes p=0,1. Each thread runs
    // TWO sequences: seqA = slot, seqB = slot + 2048.
    const int tid = blockIdx.x * 32 + threadIdx.x;
    const int slot = tid >> 1;              // 0..2047
    const int p = tid & 1;
    const int seqA = slot;
    const int seqB = slot + (B_DIM / 2);

    // Gate rows for lane p (PyTorch i,f,g,o order, H=2): gr = 2r + p.
    // Weights are shared by both sequences.
    float w[4][6], whO[4], whP[4], bs[4];
#pragma unroll
    for (int r = 0; r < 4; r++) {
        const int gr = 2 * r + p;
        const float s = (r == 2) ? 1.0f : 0.5f;   // g-gate unscaled
#pragma unroll
        for (int i = 0; i < 6; i++) w[r][i] = s * w_ih[gr * 6 + i];
        whO[r] = s * w_hh[gr * 2 + p];
        whP[r] = s * w_hh[gr * 2 + (1 - p)];
        bs[r] = s * (b_ih[gr] + b_hh[gr]);
    }

    const float4* xa4 = (const float4*)(x + (size_t)seqA * (T_DIM * I_DIM));
    const float4* xb4 = (const float4*)(x + (size_t)seqB * (T_DIM * I_DIM));

    float cA = 0.f, hA = 0.f, hpA = 0.f;
    float cB = 0.f, hB = 0.f, hpB = 0.f;

    // 4 steps per chunk = 6 float4 per sequence. Double buffer per sequence,
    // compile-time buffer index via unroll-2.
    const int NCH = T_DIM / 4;  // 512
    float4 bufA[2][6], bufB[2][6];
#pragma unroll
    for (int i = 0; i < 6; i++) { bufA[0][i] = xa4[i]; bufB[0][i] = xb4[i]; }

#pragma unroll 2
    for (int k = 0; k < NCH; k++) {
        const int cur = k & 1, nxt = cur ^ 1;
        const int kn = (k + 1 < NCH) ? (k + 1) : k;
        const float4* na = xa4 + 6 * kn;
        const float4* nb = xb4 + 6 * kn;
#pragma unroll
        for (int i = 0; i < 6; i++) { bufA[nxt][i] = na[i]; bufB[nxt][i] = nb[i]; }
        if (k + 16 < NCH) {
            asm volatile("prefetch.global.L2 [%0];" :: "l"(xa4 + 6 * (k + 16)));
            asm volatile("prefetch.global.L2 [%0];" :: "l"(xb4 + 6 * (k + 16)));
        }

        const float4 a0 = bufA[cur][0], a1 = bufA[cur][1], a2 = bufA[cur][2],
                     a3 = bufA[cur][3], a4 = bufA[cur][4], a5 = bufA[cur][5];
        const float4 b0 = bufB[cur][0], b1 = bufB[cur][1], b2 = bufB[cur][2],
                     b3 = bufB[cur][3], b4 = bufB[cur][4], b5 = bufB[cur][5];

        // Interleave A and B: each sequence's chain stalls are filled by the
        // other sequence's independent work.
        lstm_step(a0.x, a0.y, a0.z, a0.w, a1.x, a1.y, w, whO, whP, bs, cA, hA, hpA);
        lstm_step(b0.x, b0.y, b0.z, b0.w, b1.x, b1.y, w, whO, whP, bs, cB, hB, hpB);
        lstm_step(a1.z, a1.w, a2.x, a2.y, a2.z, a2.w, w, whO, whP, bs, cA, hA, hpA);
        lstm_step(b1.z, b1.w, b2.x, b2.y, b2.z, b2.w, w, whO, whP, bs, cB, hB, hpB);
        lstm_step(a3.x, a3.y, a3.z, a3.w, a4.x, a4.y, w, whO, whP, bs, cA, hA, hpA);
        lstm_step(b3.x, b3.y, b3.z, b3.w, b4.x, b4.y, w, whO, whP, bs, cB, hB, hpB);
        lstm_step(a4.z, a4.w, a5.x, a5.y, a5.z, a5.w, w, whO, whP, bs, cA, hA, hpA);
        lstm_step(b4.z, b4.w, b5.x, b5.y, b5.z, b5.w, w, whO, whP, bs, cB, hB, hpB);
    }

    // Head on even threads (they hold h0 = h_own, h1 = h_peer) for both seqs.
    if (p == 0) {
        const float rA0 = fmaxf(hA, 0.f), rA1 = fmaxf(hpA, 0.f);
        const float rB0 = fmaxf(hB, 0.f), rB1 = fmaxf(hpB, 0.f);
        float accA = fc_b[0], accB = fc_b[0];
#pragma unroll 8
        for (int j = 0; j < 128; j++) {
            const float2 wv = ((const float2*)fc1_w)[j];
            const float bj = fc1_b[j];
            const float fw = fc_w[j];
            float vA = fmaf(wv.x, rA0, fmaf(wv.y, rA1, bj));
            float vB = fmaf(wv.x, rB0, fmaf(wv.y, rB1, bj));
            accA = fmaf(fmaxf(vA, 0.f), fw, accA);
            accB = fmaf(fmaxf(vB, 0.f), fw, accB);
        }
        out[seqA] = accA;
        out[seqB] = accB;
    }
}

extern "C" void kernel_launch(void* const* d_in, const int* in_sizes, int n_in,
                              void* d_out, int out_size) {
    (void)in_sizes; (void)n_in; (void)out_size;
    lstm_fused_kernel<<<(B_DIM * 2 / 2) / 32, 32>>>(   // 4096 threads
        (const float*)d_in[0],  // x
        (const float*)d_in[1],  // w_ih
        (const float*)d_in[2],  // w_hh
        (const float*)d_in[3],  // b_ih
        (const float*)d_in[4],  // b_hh
        (const float*)d_in[5],  // fc1_w
        (const float*)d_in[6],  // fc1_b
        (const float*)d_in[7],  // fc_w
        (const float*)d_in[8],  // fc_b
        (float*)d_out);
}

// round 8
// speedup vs baseline: 1.3532x; 1.3532x over previous
#include <cuda_runtime.h>

// LSTM1: B=4096, T=2048, I=6, H=2. Two threads per sequence (parity p owns
// hidden lane p), 8192 threads = 256 warps. Chain-bound (~105 cyc/step at
// ~1GHz: MUFU stagger -> c -> tanh(c) -> h -> shfl -> h-FMAs). This round
// shortens the chain algebraically:
//   f*c      = 0.5*(tf*c + c)            [fmaf(tf,c,c)]
//   i*g      = 0.5*(ti*tg + tg)          [fmaf(ti,tg,tg)]
//   c'       = 0.5*cA + 0.5*cB
//   h_un=2h  = tc*(1+to) = fmaf(to,tc,tc)  -- 0.5 folded into Wh and head.
// Gate pre-activations for sigmoid rows keep the 0.5 input-fold
// (sigmoid(z) = 0.5*tanh(0.5z)+0.5), so raw tanh outputs are used directly.

#define B_DIM 4096
#define T_DIM 2048
#define I_DIM 6

__device__ __forceinline__ float tanh_ap(float x) {
    float y; asm("tanh.approx.f32 %0, %1;" : "=f"(y) : "f"(x)); return y;
}

// One step for one h-lane. Rows r: 0=i, 1=f, 2=g, 3=o.
// whO/whP include BOTH the sigmoid 0.5 input-fold (rows i,f,o) AND the 0.5
// from h_un = 2h. State carried: c (true scale), h_un (= 2h).
__device__ __forceinline__ void lstm_step(
    float x0, float x1, float x2, float x3, float x4, float x5,
    const float (&w)[4][6], const float (&whO)[4], const float (&whP)[4],
    const float (&bs)[4],
    float& c, float& hu_own, float& hu_peer)
{
    float g[4];
#pragma unroll
    for (int r = 0; r < 4; r++) {
        float a = fmaf(x0, w[r][0], bs[r]);
        a = fmaf(x1, w[r][1], a);
        a = fmaf(x2, w[r][2], a);
        float b2 = x3 * w[r][3];
        b2 = fmaf(x4, w[r][4], b2);
        b2 = fmaf(x5, w[r][5], b2);
        a = a + b2;
        a = fmaf(hu_own, whO[r], a);
        a = fmaf(hu_peer, whP[r], a);   // peer term last (freshest value)
    g[r] = a;
    }
    // MUFU order: g first (feeds i*g), then i, f, o.
    const float tg = tanh_ap(g[2]);
    const float ti = tanh_ap(g[0]);
    const float tf = tanh_ap(g[1]);
    const float to = tanh_ap(g[3]);

    const float cB = fmaf(ti, tg, tg);      // 2*(i*g)
    const float cA = fmaf(tf, c, c);        // 2*(f*c)
    c = fmaf(cA, 0.5f, 0.5f * cB);          // true c
    const float tc = tanh_ap(c);
    hu_own = fmaf(to, tc, tc);              // 2*h
    hu_peer = __shfl_xor_sync(0xFFFFFFFFu, hu_own, 1);
}

__global__ void __launch_bounds__(64, 1) lstm_fused_kernel(
    const float* __restrict__ x,
    const float* __restrict__ w_ih, const float* __restrict__ w_hh,
    const float* __restrict__ b_ih, const float* __restrict__ b_hh,
    const float* __restrict__ fc1_w, const float* __restrict__ fc1_b,
    const float* __restrict__ fc_w, const float* __restrict__ fc_b,
    float* __restrict__ out)
{
    const int tid = blockIdx.x * 64 + threadIdx.x;   // 8192 threads
    const int seq = tid >> 1;
    const int p = tid & 1;

    // Gate rows for lane p (PyTorch i,f,g,o order, H=2): gr = 2r + p.
    // x-weights/bias: sigmoid rows (i,f,o) pre-scaled 0.5.
    // h-weights: additionally scaled 0.5 for the h_un = 2h convention.
    float w[4][6], whO[4], whP[4], bs[4];
#pragma unroll
    for (int r = 0; r < 4; r++) {
        const int gr = 2 * r + p;
        const float s = (r == 2) ? 1.0f : 0.5f;      // sigmoid input fold
        const float sh = s * 0.5f;                   // + h_un fold
#pragma unroll
        for (int i = 0; i < 6; i++) w[r][i] = s * w_ih[gr * 6 + i];
        whO[r] = sh * w_hh[gr * 2 + p];
        whP[r] = sh * w_hh[gr * 2 + (1 - p)];
        bs[r] = s * (b_ih[gr] + b_hh[gr]);
    }

    const float4* xb4 = (const float4*)(x + (size_t)seq * (T_DIM * I_DIM));
    float c = 0.f, hu_own = 0.f, hu_peer = 0.f;

    // 4 steps per chunk = 6 float4. Double buffer, compile-time index.
    const int NCH = T_DIM / 4;  // 512
    float4 buf[2][6];
#pragma unroll
    for (int i = 0; i < 6; i++) buf[0][i] = xb4[i];

#pragma unroll 2
    for (int k = 0; k < NCH; k++) {
        const int cur = k & 1, nxt = cur ^ 1;
        const int kn = (k + 1 < NCH) ? (k + 1) : k;
        const float4* nb = xb4 + 6 * kn;
#pragma unroll
        for (int i = 0; i < 6; i++) buf[nxt][i] = nb[i];
        if (k + 16 < NCH)
            asm volatile("prefetch.global.L2 [%0];" :: "l"(xb4 + 6 * (k + 16)));

        const float4 f0 = buf[cur][0], f1 = buf[cur][1], f2 = buf[cur][2],
                     f3 = buf[cur][3], f4 = buf[cur][4], f5 = buf[cur][5];
        lstm_step(f0.x, f0.y, f0.z, f0.w, f1.x, f1.y,
                  w, whO, whP, bs, c, hu_own, hu_peer);
        lstm_step(f1.z, f1.w, f2.x, f2.y, f2.z, f2.w,
                  w, whO, whP, bs, c, hu_own, hu_peer);
        lstm_step(f3.x, f3.y, f3.z, f3.w, f4.x, f4.y,
                  w, whO, whP, bs, c, hu_own, hu_peer);
        lstm_step(f4.z, f4.w, f5.x, f5.y, f5.z, f5.w,
                  w, whO, whP, bs, c, hu_own, hu_peer);
    }

    // Head on even threads. True h = 0.5 * h_un (same sign, so relu first).
    if (p == 0) {
        const float r0 = 0.5f * fmaxf(hu_own, 0.f);
        const float r1 = 0.5f * fmaxf(hu_peer, 0.f);
        float acc = fc_b[0];
#pragma unroll 8
        for (int j = 0; j < 128; j++) {
            const float2 wv = ((const float2*)fc1_w)[j];
            float v = fmaf(wv.x, r0, fmaf(wv.y, r1, fc1_b[j]));
            v = fmaxf(v, 0.f);
            acc = fmaf(v, fc_w[j], acc);
        }
        out[seq] = acc;
    }
}

extern "C" void kernel_launch(void* const* d_in, const int* in_sizes, int n_in,
                              void* d_out, int out_size) {
    (void)in_sizes; (void)n_in; (void)out_size;
    lstm_fused_kernel<<<(2 * B_DIM) / 64, 64>>>(
        (const float*)d_in[0],  // x
        (const float*)d_in[1],  // w_ih
        (const float*)d_in[2],  // w_hh
        (const float*)d_in[3],  // b_ih
        (const float*)d_in[4],  // b_hh
        (const float*)d_in[5],  // fc1_w
        (const float*)d_in[6],  // fc1_b
        (const float*)d_in[7],  // fc_w
        (const float*)d_in[8],  // fc_b
        (float*)d_out);
}